// round 4
// baseline (speedup 1.0000x reference)
#include <cuda_runtime.h>
#include <math.h>

#define ENT   9
#define INNER 64
#define BB    16
#define SS    512
#define HH    768
#define ND    (ENT * INNER * 2)   // 1152
#define NEG_INF_F 1000000000000.0f

typedef unsigned long long u64;

__device__ __forceinline__ u64 bcast2(float x) {
    u64 r; asm("mov.b64 %0, {%1, %1};" : "=l"(r) : "f"(x)); return r;
}
__device__ __forceinline__ void ffma2(u64 &d, u64 a, u64 b) {
    asm("fma.rn.f32x2 %0, %1, %2, %0;" : "+l"(d) : "l"(a), "l"(b));
}
__device__ __forceinline__ float2 unpack2(u64 v) {
    float2 f; asm("mov.b64 {%0, %1}, %2;" : "=f"(f.x), "=f"(f.y) : "l"(v)); return f;
}

// Scratch for roped Q/K in [B, ENT, S, INNER] layout (contiguous per (b,h))
__device__ float g_q[BB * ENT * SS * INNER];
__device__ float g_k[BB * ENT * SS * INNER];

// ---------------------------------------------------------------------------
// Kernel A: proj = X @ W + b, interleaved RoPE, scatter to g_q / g_k.
// 128x128 tile, Ktile=16, 256 threads, 8x8 microtile, packed f32x2 FMA.
// A tile stored DUPLICATED in smem so a-broadcast pairs are direct LDS.64.
// B pairs come free from reinterpreting float4 loads as ulonglong2.
// Single-sync double buffering.
// ---------------------------------------------------------------------------
__global__ __launch_bounds__(256) void proj_rope_kernel(
    const float* __restrict__ X,      // [8192, 768]
    const float* __restrict__ W,      // [768, 1152]
    const float* __restrict__ bias)   // [1152]
{
    __shared__ __align__(16) float At2[2][16][256]; // [k][2m] duplicated
    __shared__ __align__(16) float Bs[2][16][128];  // [k][n]

    const int tid = threadIdx.x;
    const int tx  = tid & 15;
    const int ty  = tid >> 4;
    const int m0  = blockIdx.y * 128;
    const int n0  = blockIdx.x * 128;

    u64 acc[8][4];
    #pragma unroll
    for (int i = 0; i < 8; i++)
        #pragma unroll
        for (int j = 0; j < 4; j++) acc[i][j] = 0ull;

    // thread's fixed load slots
    const int am0 = tid >> 2;            // A row (0..63) for i=0, +64 for i=1
    const int ac0 = (tid & 3) * 4;       // A col
    const int br0 = tid >> 5;            // B row (0..7) for i=0, +8 for i=1
    const int bc0 = (tid & 31) * 4;      // B col

    float4 ra[2], rb[2];
    #pragma unroll
    for (int i = 0; i < 2; i++) {
        ra[i] = *reinterpret_cast<const float4*>(&X[(m0 + am0 + i * 64) * HH + ac0]);
        rb[i] = *reinterpret_cast<const float4*>(&W[(br0 + i * 8) * ND + n0 + bc0]);
    }

    // store tile 0 into buffer 0
    #pragma unroll
    for (int i = 0; i < 2; i++) {
        const int am = am0 + i * 64;
        *reinterpret_cast<u64*>(&At2[0][ac0 + 0][2 * am]) = bcast2(ra[i].x);
        *reinterpret_cast<u64*>(&At2[0][ac0 + 1][2 * am]) = bcast2(ra[i].y);
        *reinterpret_cast<u64*>(&At2[0][ac0 + 2][2 * am]) = bcast2(ra[i].z);
        *reinterpret_cast<u64*>(&At2[0][ac0 + 3][2 * am]) = bcast2(ra[i].w);
        *reinterpret_cast<float4*>(&Bs[0][br0 + i * 8][bc0]) = rb[i];
    }
    __syncthreads();

    const int NT = HH / 16;   // 48
    for (int t = 0; t < NT; t++) {
        const int buf = t & 1;
        if (t < NT - 1) {
            const int k0 = (t + 1) * 16;
            #pragma unroll
            for (int i = 0; i < 2; i++) {
                ra[i] = *reinterpret_cast<const float4*>(&X[(m0 + am0 + i * 64) * HH + k0 + ac0]);
                rb[i] = *reinterpret_cast<const float4*>(&W[(k0 + br0 + i * 8) * ND + n0 + bc0]);
            }
        }

        #pragma unroll
        for (int kk = 0; kk < 16; kk++) {
            u64 ap[8];
            #pragma unroll
            for (int i = 0; i < 8; i++)
                ap[i] = *reinterpret_cast<const u64*>(&At2[buf][kk][2 * (ty * 8 + i)]);
            ulonglong2 b0 = *reinterpret_cast<const ulonglong2*>(&Bs[buf][kk][tx * 8]);
            ulonglong2 b1 = *reinterpret_cast<const ulonglong2*>(&Bs[buf][kk][tx * 8 + 4]);
            u64 bp[4] = { b0.x, b0.y, b1.x, b1.y };
            #pragma unroll
            for (int i = 0; i < 8; i++)
                #pragma unroll
                for (int j = 0; j < 4; j++)
                    ffma2(acc[i][j], ap[i], bp[j]);
        }

        if (t < NT - 1) {
            const int nb = buf ^ 1;
            #pragma unroll
            for (int i = 0; i < 2; i++) {
                const int am = am0 + i * 64;
                *reinterpret_cast<u64*>(&At2[nb][ac0 + 0][2 * am]) = bcast2(ra[i].x);
                *reinterpret_cast<u64*>(&At2[nb][ac0 + 1][2 * am]) = bcast2(ra[i].y);
                *reinterpret_cast<u64*>(&At2[nb][ac0 + 2][2 * am]) = bcast2(ra[i].z);
                *reinterpret_cast<u64*>(&At2[nb][ac0 + 3][2 * am]) = bcast2(ra[i].w);
                *reinterpret_cast<float4*>(&Bs[nb][br0 + i * 8][bc0]) = rb[i];
            }
        }
        __syncthreads();
    }

    // Epilogue: bias + interleaved RoPE, scatter to g_q / g_k.
    const int ncol0 = n0 + tx * 8;
    const int head  = ncol0 / 128;
    const int w0    = ncol0 & 127;
    const bool is_q = (w0 < 64);
    const int d0    = is_q ? w0 : (w0 - 64);   // multiple of 8
    float* dst = is_q ? g_q : g_k;

    #pragma unroll
    for (int i = 0; i < 8; i++) {
        const int m = m0 + ty * 8 + i;
        const int b = m >> 9;
        const int s = m & 511;
        #pragma unroll
        for (int p = 0; p < 4; p++) {
            const int d  = d0 + 2 * p;
            const int pi = d >> 1;
            float2 v = unpack2(acc[i][p]);
            const float v0 = v.x + bias[ncol0 + 2 * p];
            const float v1 = v.y + bias[ncol0 + 2 * p + 1];
            const float freq = exp2f(-0.41524101186092f * (float)pi);
            float sn, cs;
            sincosf((float)s * freq, &sn, &cs);
            float2 o;
            o.x = v0 * cs - v1 * sn;
            o.y = v1 * cs + v0 * sn;
            const int base = (((b * ENT + head) * SS) + s) * INNER + d;
            *reinterpret_cast<float2*>(&dst[base]) = o;
        }
    }
}

// ---------------------------------------------------------------------------
// Kernel B: per (b,h): logits = Q K^T, mask + causal + scale.
// 128x128 tile, K=64 fully staged. Q tile duplicated ([d][2m], pad 258);
// K tile transposed with float4-granule XOR swizzle (conflict-free).
// 8x8 microtile on f32x2 FMA. ~96.5 KB dynamic smem, 2 blocks/SM.
// ---------------------------------------------------------------------------
#define QROW 258
__global__ __launch_bounds__(256) void qk_kernel(
    const float* __restrict__ mask,   // [16, 512]
    float* __restrict__ out)          // [16, 9, 512, 512]
{
    extern __shared__ __align__(16) float sm[];
    float (*Qt2)[QROW] = reinterpret_cast<float(*)[QROW]>(sm);          // [d][2m] dup
    float (*Kt)[128]   = reinterpret_cast<float(*)[128]>(sm + 64 * QROW); // [d][n] swizzled

    const int bz = blockIdx.z;        // b*9 + h
    const int b  = bz / ENT;
    const int m0 = blockIdx.y * 128;
    const int n0 = blockIdx.x * 128;

    const int tid = threadIdx.x;
    const int tx  = tid & 15;
    const int ty  = tid >> 4;

    const float* Qb = g_q + (size_t)bz * SS * INNER;
    const float* Kb = g_k + (size_t)bz * SS * INNER;

    // stage tiles: Q duplicated-transposed, K swizzle-transposed
    #pragma unroll
    for (int i = 0; i < 8; i++) {
        int v = tid + i * 256;             // 0..2047
        int r = v >> 4, c4 = (v & 15) * 4; // 128 rows x 64 dims
        float4 q = *reinterpret_cast<const float4*>(&Qb[(m0 + r) * INNER + c4]);
        *reinterpret_cast<u64*>(&Qt2[c4 + 0][2 * r]) = bcast2(q.x);
        *reinterpret_cast<u64*>(&Qt2[c4 + 1][2 * r]) = bcast2(q.y);
        *reinterpret_cast<u64*>(&Qt2[c4 + 2][2 * r]) = bcast2(q.z);
        *reinterpret_cast<u64*>(&Qt2[c4 + 3][2 * r]) = bcast2(q.w);

        float4 k = *reinterpret_cast<const float4*>(&Kb[(n0 + r) * INNER + c4]);
        const int col4 = r >> 2;
        const int sub  = r & 3;
        Kt[c4 + 0][((col4 ^ ((c4 + 0) & 31)) << 2) + sub] = k.x;
        Kt[c4 + 1][((col4 ^ ((c4 + 1) & 31)) << 2) + sub] = k.y;
        Kt[c4 + 2][((col4 ^ ((c4 + 2) & 31)) << 2) + sub] = k.z;
        Kt[c4 + 3][((col4 ^ ((c4 + 3) & 31)) << 2) + sub] = k.w;
    }
    __syncthreads();

    u64 acc[8][4];
    #pragma unroll
    for (int i = 0; i < 8; i++)
        #pragma unroll
        for (int j = 0; j < 4; j++) acc[i][j] = 0ull;

    #pragma unroll 8
    for (int kk = 0; kk < 64; kk++) {
        u64 ap[8];
        #pragma unroll
        for (int i = 0; i < 8; i++)
            ap[i] = *reinterpret_cast<const u64*>(&Qt2[kk][2 * (ty * 8 + i)]);
        const int s = kk & 31;
        const ulonglong2* krow = reinterpret_cast<const ulonglong2*>(Kt[kk]);
        ulonglong2 b0 = krow[(tx * 2) ^ s];
        ulonglong2 b1 = krow[(tx * 2 + 1) ^ s];
        u64 bp[4] = { b0.x, b0.y, b1.x, b1.y };
        #pragma unroll
        for (int i = 0; i < 8; i++)
            #pragma unroll
            for (int j = 0; j < 4; j++)
                ffma2(acc[i][j], ap[i], bp[j]);
    }

    float pads[8];
    #pragma unroll
    for (int j = 0; j < 8; j++) pads[j] = mask[b * SS + n0 + tx * 8 + j];

    #pragma unroll
    for (int i = 0; i < 8; i++) {
        const int m = m0 + ty * 8 + i;
        float tmp[8];
        #pragma unroll
        for (int j = 0; j < 4; j++) {
            float2 v = unpack2(acc[i][j]);
            const int n_lo = n0 + tx * 8 + 2 * j;
            float lo = v.x * pads[2 * j]     - (1.0f - pads[2 * j])     * NEG_INF_F;
            float hi = v.y * pads[2 * j + 1] - (1.0f - pads[2 * j + 1]) * NEG_INF_F;
            if (m > n_lo)     lo -= NEG_INF_F;
            if (m > n_lo + 1) hi -= NEG_INF_F;
            tmp[2 * j]     = lo * 0.125f;
            tmp[2 * j + 1] = hi * 0.125f;
        }
        float4 v0 = make_float4(tmp[0], tmp[1], tmp[2], tmp[3]);
        float4 v1 = make_float4(tmp[4], tmp[5], tmp[6], tmp[7]);
        float* base = &out[((size_t)bz * SS + m) * SS + n0 + tx * 8];
        *reinterpret_cast<float4*>(base)     = v0;
        *reinterpret_cast<float4*>(base + 4) = v1;
    }
}

extern "C" void kernel_launch(void* const* d_in, const int* in_sizes, int n_in,
                              void* d_out, int out_size) {
    const float* X    = (const float*)d_in[0];  // [16,512,768]
    const float* msk  = (const float*)d_in[1];  // [16,512]
    const float* W    = (const float*)d_in[2];  // [768,1152]
    const float* bias = (const float*)d_in[3];  // [1152]
    float* out = (float*)d_out;                 // [16,9,512,512]

    dim3 gridA(ND / 128, (BB * SS) / 128);      // (9, 64)
    proj_rope_kernel<<<gridA, 256>>>(X, W, bias);

    const int qk_smem = (64 * QROW + 64 * 128) * 4;  // 98816 B
    cudaFuncSetAttribute(qk_kernel, cudaFuncAttributeMaxDynamicSharedMemorySize, qk_smem);
    dim3 gridB(SS / 128, SS / 128, BB * ENT);   // (4, 4, 144)
    qk_kernel<<<gridB, 256, qk_smem>>>(msk, out);
}

// round 5
// speedup vs baseline: 3.2784x; 3.2784x over previous
#include <cuda_runtime.h>
#include <cuda_bf16.h>
#include <math.h>
#include <stdint.h>

#define ENT   9
#define INNER 64
#define BB    16
#define SS    512
#define HH    768
#define ND    (ENT * INNER * 2)   // 1152
#define NEG_INF_F 1000000000000.0f

// Roped Q/K scratch, bf16, [B, ENT, S, INNER]
__device__ __nv_bfloat16 g_q[BB * ENT * SS * INNER];
__device__ __nv_bfloat16 g_k[BB * ENT * SS * INNER];

__device__ __forceinline__ uint32_t smem_u32(const void* p) {
    return (uint32_t)__cvta_generic_to_shared(p);
}
__device__ __forceinline__ uint32_t pk_bf2(float lo, float hi) {
    uint32_t r; asm("cvt.rn.bf16x2.f32 %0, %1, %2;" : "=r"(r) : "f"(hi), "f"(lo)); return r;
}
__device__ __forceinline__ void ldsm4(uint32_t* r, uint32_t addr) {
    asm volatile("ldmatrix.sync.aligned.m8n8.x4.shared.b16 {%0,%1,%2,%3}, [%4];"
        : "=r"(r[0]), "=r"(r[1]), "=r"(r[2]), "=r"(r[3]) : "r"(addr));
}
__device__ __forceinline__ void ldsm4t(uint32_t* r, uint32_t addr) {
    asm volatile("ldmatrix.sync.aligned.m8n8.x4.trans.shared.b16 {%0,%1,%2,%3}, [%4];"
        : "=r"(r[0]), "=r"(r[1]), "=r"(r[2]), "=r"(r[3]) : "r"(addr));
}
__device__ __forceinline__ void mma_bf16(float* c, const uint32_t* a, uint32_t b0, uint32_t b1) {
    asm volatile("mma.sync.aligned.m16n8k16.row.col.f32.bf16.bf16.f32 "
        "{%0,%1,%2,%3}, {%4,%5,%6,%7}, {%8,%9}, {%0,%1,%2,%3};"
        : "+f"(c[0]), "+f"(c[1]), "+f"(c[2]), "+f"(c[3])
        : "r"(a[0]), "r"(a[1]), "r"(a[2]), "r"(a[3]), "r"(b0), "r"(b1));
}

// ---------------------------------------------------------------------------
// Kernel A: proj = X @ W + b (bf16 HMMA), interleaved RoPE, bf16 scatter.
// Block 128x128, ktile 16, 8 warps in 2x4, warp tile 64x32.
// ---------------------------------------------------------------------------
#define A_STRIDE 24    // bf16 per row (16 + 8 pad) -> 48 B
#define B_STRIDE 136   // bf16 per row (128 + 8 pad) -> 272 B
__global__ __launch_bounds__(256) void proj_rope_kernel(
    const float* __restrict__ X,      // [8192, 768]
    const float* __restrict__ W,      // [768, 1152]
    const float* __restrict__ bias)   // [1152]
{
    __shared__ __align__(16) __nv_bfloat16 As[2][128][A_STRIDE];
    __shared__ __align__(16) __nv_bfloat16 Bs[2][16][B_STRIDE];

    const int tid  = threadIdx.x;
    const int lane = tid & 31;
    const int w    = tid >> 5;
    const int wm   = w >> 2;          // 0..1
    const int wn   = w & 3;           // 0..3
    const int m0   = blockIdx.y * 128;
    const int n0   = blockIdx.x * 128;

    float acc[4][4][4];
    #pragma unroll
    for (int i = 0; i < 4; i++)
        #pragma unroll
        for (int j = 0; j < 4; j++)
            #pragma unroll
            for (int r = 0; r < 4; r++) acc[i][j][r] = 0.f;

    // staging slots
    const int ax_m = tid >> 2;              // 0..63 (+64)
    const int ax_c = (tid & 3) * 4;         // 0,4,8,12
    const int bx_k = tid >> 5;              // 0..7 (+8)
    const int bx_n = (tid & 31) * 4;

    float4 ra[2], rb[2];

    const uint32_t asA = smem_u32(&As[0][0][0]);
    const uint32_t asB = smem_u32(&Bs[0][0][0]);
    // ldmatrix A: row = wm*64 + i*16 + (lane&15), col8 = (lane>>4)*8
    const uint32_t aoff = (uint32_t)((wm * 64 + (lane & 15)) * A_STRIDE + (lane >> 4) * 8) * 2;
    // ldmatrix B (trans): row = ((lane>>3)&1)*8 + (lane&7), col = wn*32 + ((lane>>4)&1)*8 (+jp*16)
    const uint32_t boff = (uint32_t)((((lane >> 3) & 1) * 8 + (lane & 7)) * B_STRIDE
                                     + wn * 32 + ((lane >> 4) & 1) * 8) * 2;

    // tile 0 loads
    {
        const float* xp = X + (size_t)(m0 + ax_m) * HH + ax_c;
        ra[0] = *reinterpret_cast<const float4*>(xp);
        ra[1] = *reinterpret_cast<const float4*>(xp + 64 * HH);
        const float* wp = W + (size_t)bx_k * ND + n0 + bx_n;
        rb[0] = *reinterpret_cast<const float4*>(wp);
        rb[1] = *reinterpret_cast<const float4*>(wp + 8 * ND);
    }
    #pragma unroll
    for (int i = 0; i < 2; i++) {
        uint2 va = make_uint2(pk_bf2(((float*)&ra[i])[0], ((float*)&ra[i])[1]),
                              pk_bf2(((float*)&ra[i])[2], ((float*)&ra[i])[3]));
        *reinterpret_cast<uint2*>(&As[0][ax_m + i * 64][ax_c]) = va;
        uint2 vb = make_uint2(pk_bf2(((float*)&rb[i])[0], ((float*)&rb[i])[1]),
                              pk_bf2(((float*)&rb[i])[2], ((float*)&rb[i])[3]));
        *reinterpret_cast<uint2*>(&Bs[0][bx_k + i * 8][bx_n]) = vb;
    }
    __syncthreads();

    const int NT = HH / 16;   // 48
    for (int t = 0; t < NT; t++) {
        const int buf = t & 1;
        if (t < NT - 1) {
            const int k0 = (t + 1) * 16;
            const float* xp = X + (size_t)(m0 + ax_m) * HH + k0 + ax_c;
            ra[0] = *reinterpret_cast<const float4*>(xp);
            ra[1] = *reinterpret_cast<const float4*>(xp + 64 * HH);
            const float* wp = W + (size_t)(k0 + bx_k) * ND + n0 + bx_n;
            rb[0] = *reinterpret_cast<const float4*>(wp);
            rb[1] = *reinterpret_cast<const float4*>(wp + 8 * ND);
        }

        uint32_t a[4][4], b[2][4];
        const uint32_t abase = asA + (uint32_t)buf * (128 * A_STRIDE * 2);
        const uint32_t bbase = asB + (uint32_t)buf * (16 * B_STRIDE * 2);
        #pragma unroll
        for (int i = 0; i < 4; i++) ldsm4(a[i], abase + aoff + i * 16 * A_STRIDE * 2);
        #pragma unroll
        for (int jp = 0; jp < 2; jp++) ldsm4t(b[jp], bbase + boff + jp * 32);
        #pragma unroll
        for (int i = 0; i < 4; i++)
            #pragma unroll
            for (int j = 0; j < 4; j++)
                mma_bf16(acc[i][j], a[i], b[j >> 1][(j & 1) * 2], b[j >> 1][(j & 1) * 2 + 1]);

        if (t < NT - 1) {
            const int nb = buf ^ 1;
            #pragma unroll
            for (int i = 0; i < 2; i++) {
                uint2 va = make_uint2(pk_bf2(((float*)&ra[i])[0], ((float*)&ra[i])[1]),
                                      pk_bf2(((float*)&ra[i])[2], ((float*)&ra[i])[3]));
                *reinterpret_cast<uint2*>(&As[nb][ax_m + i * 64][ax_c]) = va;
                uint2 vb = make_uint2(pk_bf2(((float*)&rb[i])[0], ((float*)&rb[i])[1]),
                                      pk_bf2(((float*)&rb[i])[2], ((float*)&rb[i])[3]));
                *reinterpret_cast<uint2*>(&Bs[nb][bx_k + i * 8][bx_n]) = vb;
            }
        }
        __syncthreads();
    }

    // Epilogue: bias + interleaved RoPE, bf16 scatter to g_q/g_k.
    #pragma unroll
    for (int j = 0; j < 4; j++) {
        const int n = n0 + wn * 32 + j * 8 + (lane & 3) * 2;
        const int head = n >> 7;
        const int wloc = n & 127;
        const bool is_q = (wloc < 64);
        const int d  = wloc & 63;       // even
        const int pi = d >> 1;
        const float freq = exp2f(-0.41524101186092f * (float)pi);
        const float b0f = __ldg(&bias[n]);
        const float b1f = __ldg(&bias[n + 1]);
        __nv_bfloat16* dst = is_q ? g_q : g_k;
        #pragma unroll
        for (int i = 0; i < 4; i++) {
            #pragma unroll
            for (int h = 0; h < 2; h++) {
                const int m = m0 + wm * 64 + i * 16 + (lane >> 2) + h * 8;
                const int bb = m >> 9;
                const int s  = m & 511;
                float sn, cs;
                __sincosf((float)s * freq, &sn, &cs);
                const float v0 = acc[i][j][2 * h]     + b0f;
                const float v1 = acc[i][j][2 * h + 1] + b1f;
                const float o0 = v0 * cs - v1 * sn;
                const float o1 = v1 * cs + v0 * sn;
                const int base = (((bb * ENT + head) * SS) + s) * INNER + d;
                *reinterpret_cast<uint32_t*>(&dst[base]) = pk_bf2(o0, o1);
            }
        }
    }
}

// ---------------------------------------------------------------------------
// Kernel B: per (b,h): logits = Q K^T (bf16 HMMA), mask + causal + scale.
// Block 128x128, K=64 staged once. 8 warps 2x4, warp tile 64x32.
// ---------------------------------------------------------------------------
#define Q_STRIDE 72   // bf16 per row (64 + 8 pad) -> 144 B
__global__ __launch_bounds__(256) void qk_kernel(
    const float* __restrict__ mask,   // [16, 512]
    float* __restrict__ out)          // [16, 9, 512, 512]
{
    __shared__ __align__(16) __nv_bfloat16 Qs[128][Q_STRIDE];
    __shared__ __align__(16) __nv_bfloat16 Ks[128][Q_STRIDE];

    const int bz = blockIdx.z;        // b*9 + h
    const int b  = bz / ENT;
    const int m0 = blockIdx.y * 128;
    const int n0 = blockIdx.x * 128;

    const int tid  = threadIdx.x;
    const int lane = tid & 31;
    const int w    = tid >> 5;
    const int wm   = w >> 2;
    const int wn   = w & 3;

    const __nv_bfloat16* Qb = g_q + (size_t)bz * SS * INNER;
    const __nv_bfloat16* Kb = g_k + (size_t)bz * SS * INNER;

    #pragma unroll
    for (int q = 0; q < 4; q++) {
        int v = tid + q * 256;            // 0..1023
        int r = v >> 3, c8 = (v & 7) * 8; // 128 rows x 64 cols
        *reinterpret_cast<uint4*>(&Qs[r][c8]) =
            *reinterpret_cast<const uint4*>(&Qb[(size_t)(m0 + r) * INNER + c8]);
        *reinterpret_cast<uint4*>(&Ks[r][c8]) =
            *reinterpret_cast<const uint4*>(&Kb[(size_t)(n0 + r) * INNER + c8]);
    }
    __syncthreads();

    float acc[4][4][4];
    #pragma unroll
    for (int i = 0; i < 4; i++)
        #pragma unroll
        for (int j = 0; j < 4; j++)
            #pragma unroll
            for (int r = 0; r < 4; r++) acc[i][j][r] = 0.f;

    const uint32_t asQ = smem_u32(&Qs[0][0]);
    const uint32_t asK = smem_u32(&Ks[0][0]);
    // A: row = wm*64 + i*16 + (lane&15), col8 = (lane>>4)*8 (+ks*16)
    const uint32_t aoff = (uint32_t)((wm * 64 + (lane & 15)) * Q_STRIDE + (lane >> 4) * 8) * 2;
    // B (non-trans): row = wn*32 + jp*16 + ((lane>>4)&1)*8 + (lane&7), col = ((lane>>3)&1)*8 (+ks*16)
    const uint32_t boff = (uint32_t)((wn * 32 + ((lane >> 4) & 1) * 8 + (lane & 7)) * Q_STRIDE
                                     + ((lane >> 3) & 1) * 8) * 2;

    #pragma unroll
    for (int ks = 0; ks < 4; ks++) {
        uint32_t a[4][4], bfr[2][4];
        #pragma unroll
        for (int i = 0; i < 4; i++)
            ldsm4(a[i], asQ + aoff + (uint32_t)(i * 16 * Q_STRIDE + ks * 16) * 2);
        #pragma unroll
        for (int jp = 0; jp < 2; jp++)
            ldsm4(bfr[jp], asK + boff + (uint32_t)(jp * 16 * Q_STRIDE + ks * 16) * 2);
        #pragma unroll
        for (int i = 0; i < 4; i++)
            #pragma unroll
            for (int j = 0; j < 4; j++)
                mma_bf16(acc[i][j], a[i], bfr[j >> 1][(j & 1) * 2], bfr[j >> 1][(j & 1) * 2 + 1]);
    }

    // Epilogue: mask + causal + scale, fp32 stores.
    #pragma unroll
    for (int j = 0; j < 4; j++) {
        const int n = n0 + wn * 32 + j * 8 + (lane & 3) * 2;
        const float p0 = __ldg(&mask[b * SS + n]);
        const float p1 = __ldg(&mask[b * SS + n + 1]);
        #pragma unroll
        for (int i = 0; i < 4; i++) {
            #pragma unroll
            for (int h = 0; h < 2; h++) {
                const int m = m0 + wm * 64 + i * 16 + (lane >> 2) + h * 8;
                float lo = acc[i][j][2 * h]     * p0 - (1.0f - p0) * NEG_INF_F;
                float hi = acc[i][j][2 * h + 1] * p1 - (1.0f - p1) * NEG_INF_F;
                if (m > n)     lo -= NEG_INF_F;
                if (m > n + 1) hi -= NEG_INF_F;
                float2 v = make_float2(lo * 0.125f, hi * 0.125f);
                *reinterpret_cast<float2*>(&out[((size_t)bz * SS + m) * SS + n]) = v;
            }
        }
    }
}

extern "C" void kernel_launch(void* const* d_in, const int* in_sizes, int n_in,
                              void* d_out, int out_size) {
    const float* X    = (const float*)d_in[0];  // [16,512,768]
    const float* msk  = (const float*)d_in[1];  // [16,512]
    const float* W    = (const float*)d_in[2];  // [768,1152]
    const float* bias = (const float*)d_in[3];  // [1152]
    float* out = (float*)d_out;                 // [16,9,512,512]

    dim3 gridA(ND / 128, (BB * SS) / 128);      // (9, 64)
    proj_rope_kernel<<<gridA, 256>>>(X, W, bias);

    dim3 gridB(SS / 128, SS / 128, BB * ENT);   // (4, 4, 144)
    qk_kernel<<<gridB, 256>>>(msk, out);
}

// round 6
// speedup vs baseline: 3.3250x; 1.0142x over previous
#include <cuda_runtime.h>
#include <cuda_bf16.h>
#include <math.h>
#include <stdint.h>

#define ENT   9
#define INNER 64
#define BB    16
#define SS    512
#define HH    768
#define ND    (ENT * INNER * 2)   // 1152
#define NEG_INF_F 1000000000000.0f

// bf16 copies of inputs + roped Q/K scratch
__device__ __nv_bfloat16 g_xb[BB * SS * HH];       // 6291456
__device__ __nv_bfloat16 g_wb[HH * ND];            // 884736
__device__ __nv_bfloat16 g_q[BB * ENT * SS * INNER];
__device__ __nv_bfloat16 g_k[BB * ENT * SS * INNER];

__device__ __forceinline__ uint32_t smem_u32(const void* p) {
    return (uint32_t)__cvta_generic_to_shared(p);
}
__device__ __forceinline__ uint32_t pk_bf2(float lo, float hi) {
    uint32_t r; asm("cvt.rn.bf16x2.f32 %0, %1, %2;" : "=r"(r) : "f"(hi), "f"(lo)); return r;
}
__device__ __forceinline__ void ldsm4(uint32_t* r, uint32_t addr) {
    asm volatile("ldmatrix.sync.aligned.m8n8.x4.shared.b16 {%0,%1,%2,%3}, [%4];"
        : "=r"(r[0]), "=r"(r[1]), "=r"(r[2]), "=r"(r[3]) : "r"(addr));
}
__device__ __forceinline__ void ldsm4t(uint32_t* r, uint32_t addr) {
    asm volatile("ldmatrix.sync.aligned.m8n8.x4.trans.shared.b16 {%0,%1,%2,%3}, [%4];"
        : "=r"(r[0]), "=r"(r[1]), "=r"(r[2]), "=r"(r[3]) : "r"(addr));
}
__device__ __forceinline__ void mma_bf16(float* c, const uint32_t* a, uint32_t b0, uint32_t b1) {
    asm volatile("mma.sync.aligned.m16n8k16.row.col.f32.bf16.bf16.f32 "
        "{%0,%1,%2,%3}, {%4,%5,%6,%7}, {%8,%9}, {%0,%1,%2,%3};"
        : "+f"(c[0]), "+f"(c[1]), "+f"(c[2]), "+f"(c[3])
        : "r"(a[0]), "r"(a[1]), "r"(a[2]), "r"(a[3]), "r"(b0), "r"(b1));
}
__device__ __forceinline__ void cp16(uint32_t dst, const void* src) {
    asm volatile("cp.async.cg.shared.global [%0], [%1], 16;" :: "r"(dst), "l"(src));
}
__device__ __forceinline__ void cp_commit() { asm volatile("cp.async.commit_group;"); }
template<int N> __device__ __forceinline__ void cp_wait() {
    asm volatile("cp.async.wait_group %0;" :: "n"(N));
}

// ---------------------------------------------------------------------------
// Kernel 0: fp32 -> bf16 conversion of X and W.
// ---------------------------------------------------------------------------
__global__ __launch_bounds__(256) void convert_kernel(
    const float* __restrict__ X, const float* __restrict__ W)
{
    const int xq = (BB * SS * HH) / 4;   // 1572864
    const int wq = (HH * ND) / 4;        //  221184
    int i = blockIdx.x * blockDim.x + threadIdx.x;
    if (i < xq) {
        float4 v = *reinterpret_cast<const float4*>(X + 4 * i);
        uint2 p = make_uint2(pk_bf2(v.x, v.y), pk_bf2(v.z, v.w));
        *reinterpret_cast<uint2*>(g_xb + 4 * i) = p;
    } else if (i < xq + wq) {
        int j = i - xq;
        float4 v = *reinterpret_cast<const float4*>(W + 4 * j);
        uint2 p = make_uint2(pk_bf2(v.x, v.y), pk_bf2(v.z, v.w));
        *reinterpret_cast<uint2*>(g_wb + 4 * j) = p;
    }
}

// ---------------------------------------------------------------------------
// Kernel A: proj = Xb @ Wb + b (bf16 HMMA), interleaved RoPE, bf16 scatter.
// Block 128x128, ktile 32, cp.async double buffer, 8 warps 2x4, warp 64x32.
// ---------------------------------------------------------------------------
#define A_STRIDE 40    // bf16 per row (32 + 8 pad) -> 80 B (5 x 16B, odd)
#define B_STRIDE 136   // bf16 per row (128 + 8 pad) -> 272 B (17 x 16B, odd)
__global__ __launch_bounds__(256) void proj_rope_kernel(
    const float* __restrict__ bias)   // [1152]
{
    __shared__ __align__(16) __nv_bfloat16 As[2][128][A_STRIDE];
    __shared__ __align__(16) __nv_bfloat16 Bs[2][32][B_STRIDE];

    const int tid  = threadIdx.x;
    const int lane = tid & 31;
    const int w    = tid >> 5;
    const int wm   = w >> 2;          // 0..1
    const int wn   = w & 3;           // 0..3
    const int m0   = blockIdx.y * 128;
    const int n0   = blockIdx.x * 128;

    float acc[4][4][4];
    #pragma unroll
    for (int i = 0; i < 4; i++)
        #pragma unroll
        for (int j = 0; j < 4; j++)
            #pragma unroll
            for (int r = 0; r < 4; r++) acc[i][j][r] = 0.f;

    // cp.async slots: A 128x32 (4 chunks/row), B 32x128 (16 chunks/row)
    const int ar0 = tid >> 2,  ac0 = (tid & 3) * 8;    // + second chunk at +64 rows
    const int br0 = tid >> 4,  bc0 = (tid & 15) * 8;   // + second chunk at +16 rows

    const uint32_t asA = smem_u32(&As[0][0][0]);
    const uint32_t asB = smem_u32(&Bs[0][0][0]);

    auto stage = [&](int buf, int t) {
        const int k0 = t * 32;
        const uint32_t aB = asA + (uint32_t)buf * (128 * A_STRIDE * 2);
        const uint32_t bB = asB + (uint32_t)buf * (32 * B_STRIDE * 2);
        cp16(aB + (uint32_t)(ar0 * A_STRIDE + ac0) * 2,
             g_xb + (size_t)(m0 + ar0) * HH + k0 + ac0);
        cp16(aB + (uint32_t)((ar0 + 64) * A_STRIDE + ac0) * 2,
             g_xb + (size_t)(m0 + ar0 + 64) * HH + k0 + ac0);
        cp16(bB + (uint32_t)(br0 * B_STRIDE + bc0) * 2,
             g_wb + (size_t)(k0 + br0) * ND + n0 + bc0);
        cp16(bB + (uint32_t)((br0 + 16) * B_STRIDE + bc0) * 2,
             g_wb + (size_t)(k0 + br0 + 16) * ND + n0 + bc0);
    };

    // ldmatrix base offsets
    const uint32_t aoff = (uint32_t)((wm * 64 + (lane & 15)) * A_STRIDE + (lane >> 4) * 8) * 2;
    const uint32_t boff = (uint32_t)((((lane >> 3) & 1) * 8 + (lane & 7)) * B_STRIDE
                                     + wn * 32 + ((lane >> 4) & 1) * 8) * 2;

    stage(0, 0);
    cp_commit();

    const int NT = HH / 32;   // 24
    for (int t = 0; t < NT; t++) {
        const int buf = t & 1;
        if (t < NT - 1) { stage(buf ^ 1, t + 1); cp_commit(); cp_wait<1>(); }
        else           { cp_wait<0>(); }
        __syncthreads();

        const uint32_t abase = asA + (uint32_t)buf * (128 * A_STRIDE * 2);
        const uint32_t bbase = asB + (uint32_t)buf * (32 * B_STRIDE * 2);
        #pragma unroll
        for (int ks = 0; ks < 2; ks++) {
            uint32_t a[4][4], b[2][4];
            #pragma unroll
            for (int i = 0; i < 4; i++)
                ldsm4(a[i], abase + aoff + (uint32_t)(i * 16 * A_STRIDE + ks * 16) * 2);
            #pragma unroll
            for (int jp = 0; jp < 2; jp++)
                ldsm4t(b[jp], bbase + boff + (uint32_t)(ks * 16 * B_STRIDE) * 2 + jp * 32);
            #pragma unroll
            for (int i = 0; i < 4; i++)
                #pragma unroll
                for (int j = 0; j < 4; j++)
                    mma_bf16(acc[i][j], a[i], b[j >> 1][(j & 1) * 2], b[j >> 1][(j & 1) * 2 + 1]);
        }
        __syncthreads();
    }

    // Epilogue: bias + interleaved RoPE, bf16 scatter to g_q/g_k.
    #pragma unroll
    for (int j = 0; j < 4; j++) {
        const int n = n0 + wn * 32 + j * 8 + (lane & 3) * 2;
        const int head = n >> 7;
        const int wloc = n & 127;
        const bool is_q = (wloc < 64);
        const int d  = wloc & 63;       // even
        const int pi = d >> 1;
        const float freq = exp2f(-0.41524101186092f * (float)pi);
        const float b0f = __ldg(&bias[n]);
        const float b1f = __ldg(&bias[n + 1]);
        __nv_bfloat16* dst = is_q ? g_q : g_k;
        #pragma unroll
        for (int i = 0; i < 4; i++) {
            #pragma unroll
            for (int h = 0; h < 2; h++) {
                const int m = m0 + wm * 64 + i * 16 + (lane >> 2) + h * 8;
                const int bb = m >> 9;
                const int s  = m & 511;
                float sn, cs;
                __sincosf((float)s * freq, &sn, &cs);
                const float v0 = acc[i][j][2 * h]     + b0f;
                const float v1 = acc[i][j][2 * h + 1] + b1f;
                const float o0 = v0 * cs - v1 * sn;
                const float o1 = v1 * cs + v0 * sn;
                const int base = (((bb * ENT + head) * SS) + s) * INNER + d;
                *reinterpret_cast<uint32_t*>(&dst[base]) = pk_bf2(o0, o1);
            }
        }
    }
}

// ---------------------------------------------------------------------------
// Kernel B: per (b,h): logits = Q K^T (bf16 HMMA), mask + causal + scale.
// Block 128x128, K=64 staged once. 8 warps 2x4, warp tile 64x32.
// Streaming fp32 stores (st.global.cs).
// ---------------------------------------------------------------------------
#define Q_STRIDE 72   // bf16 per row (64 + 8 pad) -> 144 B (9 x 16B, odd)
__global__ __launch_bounds__(256) void qk_kernel(
    const float* __restrict__ mask,   // [16, 512]
    float* __restrict__ out)          // [16, 9, 512, 512]
{
    __shared__ __align__(16) __nv_bfloat16 Qs[128][Q_STRIDE];
    __shared__ __align__(16) __nv_bfloat16 Ks[128][Q_STRIDE];

    const int bz = blockIdx.z;        // b*9 + h
    const int b  = bz / ENT;
    const int m0 = blockIdx.y * 128;
    const int n0 = blockIdx.x * 128;

    const int tid  = threadIdx.x;
    const int lane = tid & 31;
    const int w    = tid >> 5;
    const int wm   = w >> 2;
    const int wn   = w & 3;

    const __nv_bfloat16* Qb = g_q + (size_t)bz * SS * INNER;
    const __nv_bfloat16* Kb = g_k + (size_t)bz * SS * INNER;

    #pragma unroll
    for (int q = 0; q < 4; q++) {
        int v = tid + q * 256;            // 0..1023
        int r = v >> 3, c8 = (v & 7) * 8; // 128 rows x 64 cols
        *reinterpret_cast<uint4*>(&Qs[r][c8]) =
            *reinterpret_cast<const uint4*>(&Qb[(size_t)(m0 + r) * INNER + c8]);
        *reinterpret_cast<uint4*>(&Ks[r][c8]) =
            *reinterpret_cast<const uint4*>(&Kb[(size_t)(n0 + r) * INNER + c8]);
    }
    __syncthreads();

    float acc[4][4][4];
    #pragma unroll
    for (int i = 0; i < 4; i++)
        #pragma unroll
        for (int j = 0; j < 4; j++)
            #pragma unroll
            for (int r = 0; r < 4; r++) acc[i][j][r] = 0.f;

    const uint32_t asQ = smem_u32(&Qs[0][0]);
    const uint32_t asK = smem_u32(&Ks[0][0]);
    const uint32_t aoff = (uint32_t)((wm * 64 + (lane & 15)) * Q_STRIDE + (lane >> 4) * 8) * 2;
    const uint32_t boff = (uint32_t)((wn * 32 + ((lane >> 4) & 1) * 8 + (lane & 7)) * Q_STRIDE
                                     + ((lane >> 3) & 1) * 8) * 2;

    #pragma unroll
    for (int ks = 0; ks < 4; ks++) {
        uint32_t a[4][4], bfr[2][4];
        #pragma unroll
        for (int i = 0; i < 4; i++)
            ldsm4(a[i], asQ + aoff + (uint32_t)(i * 16 * Q_STRIDE + ks * 16) * 2);
        #pragma unroll
        for (int jp = 0; jp < 2; jp++)
            ldsm4(bfr[jp], asK + boff + (uint32_t)(jp * 16 * Q_STRIDE + ks * 16) * 2);
        #pragma unroll
        for (int i = 0; i < 4; i++)
            #pragma unroll
            for (int j = 0; j < 4; j++)
                mma_bf16(acc[i][j], a[i], bfr[j >> 1][(j & 1) * 2], bfr[j >> 1][(j & 1) * 2 + 1]);
    }

    // Epilogue: mask + causal + scale, streaming fp32 stores.
    #pragma unroll
    for (int j = 0; j < 4; j++) {
        const int n = n0 + wn * 32 + j * 8 + (lane & 3) * 2;
        const float p0 = __ldg(&mask[b * SS + n]);
        const float p1 = __ldg(&mask[b * SS + n + 1]);
        #pragma unroll
        for (int i = 0; i < 4; i++) {
            #pragma unroll
            for (int h = 0; h < 2; h++) {
                const int m = m0 + wm * 64 + i * 16 + (lane >> 2) + h * 8;
                float lo = acc[i][j][2 * h]     * p0 - (1.0f - p0) * NEG_INF_F;
                float hi = acc[i][j][2 * h + 1] * p1 - (1.0f - p1) * NEG_INF_F;
                if (m > n)     lo -= NEG_INF_F;
                if (m > n + 1) hi -= NEG_INF_F;
                float2 v = make_float2(lo * 0.125f, hi * 0.125f);
                __stcs(reinterpret_cast<float2*>(&out[((size_t)bz * SS + m) * SS + n]), v);
            }
        }
    }
}

extern "C" void kernel_launch(void* const* d_in, const int* in_sizes, int n_in,
                              void* d_out, int out_size) {
    const float* X    = (const float*)d_in[0];  // [16,512,768]
    const float* msk  = (const float*)d_in[1];  // [16,512]
    const float* W    = (const float*)d_in[2];  // [768,1152]
    const float* bias = (const float*)d_in[3];  // [1152]
    float* out = (float*)d_out;                 // [16,9,512,512]

    const int cvt_chunks = (BB * SS * HH + HH * ND) / 4;
    convert_kernel<<<(cvt_chunks + 255) / 256, 256>>>(X, W);

    dim3 gridA(ND / 128, (BB * SS) / 128);      // (9, 64)
    proj_rope_kernel<<<gridA, 256>>>(bias);

    dim3 gridB(SS / 128, SS / 128, BB * ENT);   // (4, 4, 144)
    qk_kernel<<<gridB, 256>>>(msk, out);
}

// round 8
// speedup vs baseline: 5.0048x; 1.5052x over previous
#include <cuda_runtime.h>
#include <cuda_bf16.h>
#include <math.h>
#include <stdint.h>

#define ENT   9
#define INNER 64
#define BB    16
#define SS    512
#define HH    768
#define ND    (ENT * INNER * 2)   // 1152
#define NEG_INF_F 1000000000000.0f

// bf16 copies of inputs + roped Q/K scratch + rope table
__device__ __nv_bfloat16 g_xb[BB * SS * HH];       // 6291456
__device__ __nv_bfloat16 g_wb[HH * ND];            //  884736
__device__ __nv_bfloat16 g_q[BB * ENT * SS * INNER];
__device__ __nv_bfloat16 g_k[BB * ENT * SS * INNER];
__device__ float g_rope[SS * 64];                  // [s][d] pairs: (cos,sin) per (s, d/2)

__device__ __forceinline__ uint32_t smem_u32(const void* p) {
    return (uint32_t)__cvta_generic_to_shared(p);
}
__device__ __forceinline__ uint32_t pk_bf2(float lo, float hi) {
    uint32_t r; asm("cvt.rn.bf16x2.f32 %0, %1, %2;" : "=r"(r) : "f"(hi), "f"(lo)); return r;
}
__device__ __forceinline__ void ldsm4(uint32_t* r, uint32_t addr) {
    asm volatile("ldmatrix.sync.aligned.m8n8.x4.shared.b16 {%0,%1,%2,%3}, [%4];"
        : "=r"(r[0]), "=r"(r[1]), "=r"(r[2]), "=r"(r[3]) : "r"(addr));
}
__device__ __forceinline__ void ldsm4t(uint32_t* r, uint32_t addr) {
    asm volatile("ldmatrix.sync.aligned.m8n8.x4.trans.shared.b16 {%0,%1,%2,%3}, [%4];"
        : "=r"(r[0]), "=r"(r[1]), "=r"(r[2]), "=r"(r[3]) : "r"(addr));
}
__device__ __forceinline__ void mma_bf16(float* c, const uint32_t* a, uint32_t b0, uint32_t b1) {
    asm volatile("mma.sync.aligned.m16n8k16.row.col.f32.bf16.bf16.f32 "
        "{%0,%1,%2,%3}, {%4,%5,%6,%7}, {%8,%9}, {%0,%1,%2,%3};"
        : "+f"(c[0]), "+f"(c[1]), "+f"(c[2]), "+f"(c[3])
        : "r"(a[0]), "r"(a[1]), "r"(a[2]), "r"(a[3]), "r"(b0), "r"(b1));
}
__device__ __forceinline__ void cp16(uint32_t dst, const void* src) {
    asm volatile("cp.async.cg.shared.global [%0], [%1], 16;" :: "r"(dst), "l"(src));
}
__device__ __forceinline__ void cp_commit() { asm volatile("cp.async.commit_group;"); }
template<int N> __device__ __forceinline__ void cp_wait() {
    asm volatile("cp.async.wait_group %0;" :: "n"(N));
}

// ---------------------------------------------------------------------------
// Prep kernels
// ---------------------------------------------------------------------------
__global__ __launch_bounds__(256) void convert_kernel(
    const float* __restrict__ X, const float* __restrict__ W)
{
    const int xq = (BB * SS * HH) / 4;   // 1572864
    const int wq = (HH * ND) / 4;        //  221184
    int i = blockIdx.x * blockDim.x + threadIdx.x;
    if (i < xq) {
        float4 v = *reinterpret_cast<const float4*>(X + 4 * (size_t)i);
        uint2 p = make_uint2(pk_bf2(v.x, v.y), pk_bf2(v.z, v.w));
        *reinterpret_cast<uint2*>(g_xb + 4 * (size_t)i) = p;
    } else if (i < xq + wq) {
        int j = i - xq;
        float4 v = *reinterpret_cast<const float4*>(W + 4 * (size_t)j);
        uint2 p = make_uint2(pk_bf2(v.x, v.y), pk_bf2(v.z, v.w));
        *reinterpret_cast<uint2*>(g_wb + 4 * (size_t)j) = p;
    }
}

__global__ __launch_bounds__(256) void rope_table_kernel() {
    int i = blockIdx.x * blockDim.x + threadIdx.x;  // 16384 = 512 * 32
    int s = i >> 5, p = i & 31;
    float freq = exp2f(-0.41524101186092f * (float)p);
    float sn, cs;
    sincosf((float)s * freq, &sn, &cs);
    g_rope[2 * i]     = cs;
    g_rope[2 * i + 1] = sn;
}

// ---------------------------------------------------------------------------
// Kernel A: proj = Xb @ Wb + b (bf16 HMMA), RoPE via table, bf16 scatter.
// Block 128x128, ktile 32, cp.async double buffer, 8 warps 2x4, warp 64x32.
// ---------------------------------------------------------------------------
#define A_STRIDE 40    // bf16 per row (32 + 8 pad)
#define B_STRIDE 136   // bf16 per row (128 + 8 pad)
__global__ __launch_bounds__(256) void proj_rope_kernel(
    const float* __restrict__ bias)   // [1152]
{
    __shared__ __align__(16) __nv_bfloat16 As[2][128][A_STRIDE];
    __shared__ __align__(16) __nv_bfloat16 Bs[2][32][B_STRIDE];

    const int tid  = threadIdx.x;
    const int lane = tid & 31;
    const int w    = tid >> 5;
    const int wm   = w >> 2;          // 0..1
    const int wn   = w & 3;           // 0..3
    const int m0   = blockIdx.y * 128;
    const int n0   = blockIdx.x * 128;

    float acc[4][4][4];
    #pragma unroll
    for (int i = 0; i < 4; i++)
        #pragma unroll
        for (int j = 0; j < 4; j++)
            #pragma unroll
            for (int r = 0; r < 4; r++) acc[i][j][r] = 0.f;

    const int ar0 = tid >> 2,  ac0 = (tid & 3) * 8;
    const int br0 = tid >> 4,  bc0 = (tid & 15) * 8;

    const uint32_t asA = smem_u32(&As[0][0][0]);
    const uint32_t asB = smem_u32(&Bs[0][0][0]);

    auto stage = [&](int buf, int t) {
        const int k0 = t * 32;
        const uint32_t aB = asA + (uint32_t)buf * (128 * A_STRIDE * 2);
        const uint32_t bB = asB + (uint32_t)buf * (32 * B_STRIDE * 2);
        cp16(aB + (uint32_t)(ar0 * A_STRIDE + ac0) * 2,
             g_xb + (size_t)(m0 + ar0) * HH + k0 + ac0);
        cp16(aB + (uint32_t)((ar0 + 64) * A_STRIDE + ac0) * 2,
             g_xb + (size_t)(m0 + ar0 + 64) * HH + k0 + ac0);
        cp16(bB + (uint32_t)(br0 * B_STRIDE + bc0) * 2,
             g_wb + (size_t)(k0 + br0) * ND + n0 + bc0);
        cp16(bB + (uint32_t)((br0 + 16) * B_STRIDE + bc0) * 2,
             g_wb + (size_t)(k0 + br0 + 16) * ND + n0 + bc0);
    };

    const uint32_t aoff = (uint32_t)((wm * 64 + (lane & 15)) * A_STRIDE + (lane >> 4) * 8) * 2;
    const uint32_t boff = (uint32_t)((((lane >> 3) & 1) * 8 + (lane & 7)) * B_STRIDE
                                     + wn * 32 + ((lane >> 4) & 1) * 8) * 2;

    stage(0, 0);
    cp_commit();

    const int NT = HH / 32;   // 24
    for (int t = 0; t < NT; t++) {
        const int buf = t & 1;
        if (t < NT - 1) { stage(buf ^ 1, t + 1); cp_commit(); cp_wait<1>(); }
        else           { cp_wait<0>(); }
        __syncthreads();

        const uint32_t abase = asA + (uint32_t)buf * (128 * A_STRIDE * 2);
        const uint32_t bbase = asB + (uint32_t)buf * (32 * B_STRIDE * 2);
        #pragma unroll
        for (int ks = 0; ks < 2; ks++) {
            uint32_t a[4][4], b[2][4];
            #pragma unroll
            for (int i = 0; i < 4; i++)
                ldsm4(a[i], abase + aoff + (uint32_t)(i * 16 * A_STRIDE + ks * 16) * 2);
            #pragma unroll
            for (int jp = 0; jp < 2; jp++)
                ldsm4t(b[jp], bbase + boff + (uint32_t)(ks * 16 * B_STRIDE) * 2 + jp * 32);
            #pragma unroll
            for (int i = 0; i < 4; i++)
                #pragma unroll
                for (int j = 0; j < 4; j++)
                    mma_bf16(acc[i][j], a[i], b[j >> 1][(j & 1) * 2], b[j >> 1][(j & 1) * 2 + 1]);
        }
        __syncthreads();
    }

    // Epilogue: bias + RoPE (table), bf16 scatter to g_q/g_k.
    #pragma unroll
    for (int j = 0; j < 4; j++) {
        const int n = n0 + wn * 32 + j * 8 + (lane & 3) * 2;
        const int head = n >> 7;
        const int wloc = n & 127;
        const bool is_q = (wloc < 64);
        const int d  = wloc & 63;       // even
        const float b0f = __ldg(&bias[n]);
        const float b1f = __ldg(&bias[n + 1]);
        __nv_bfloat16* dst = is_q ? g_q : g_k;
        #pragma unroll
        for (int i = 0; i < 4; i++) {
            #pragma unroll
            for (int h = 0; h < 2; h++) {
                const int m = m0 + wm * 64 + i * 16 + (lane >> 2) + h * 8;
                const int bb = m >> 9;
                const int s  = m & 511;
                const float2 r2 = *reinterpret_cast<const float2*>(&g_rope[s * 64 + d]);
                const float v0 = acc[i][j][2 * h]     + b0f;
                const float v1 = acc[i][j][2 * h + 1] + b1f;
                const float o0 = v0 * r2.x - v1 * r2.y;
                const float o1 = v1 * r2.x + v0 * r2.y;
                const int base = (((bb * ENT + head) * SS) + s) * INNER + d;
                *reinterpret_cast<uint32_t*>(&dst[base]) = pk_bf2(o0, o1);
            }
        }
    }
}

// ---------------------------------------------------------------------------
// Kernel B: per (b,h): logits = Q K^T (bf16 HMMA), mask + causal + scale.
// Block 128x128, K=64 staged once, 8 warps 2x4, streaming fp32 stores.
// ---------------------------------------------------------------------------
#define Q_STRIDE 72   // bf16 per row (64 + 8 pad)
__global__ __launch_bounds__(256) void qk_kernel(
    const float* __restrict__ mask,   // [16, 512]
    float* __restrict__ out)          // [16, 9, 512, 512]
{
    __shared__ __align__(16) __nv_bfloat16 Qs[128][Q_STRIDE];
    __shared__ __align__(16) __nv_bfloat16 Ks[128][Q_STRIDE];

    const int bz = blockIdx.z;
    const int b  = bz / ENT;
    const int m0 = blockIdx.y * 128;
    const int n0 = blockIdx.x * 128;

    const int tid  = threadIdx.x;
    const int lane = tid & 31;
    const int w    = tid >> 5;
    const int wm   = w >> 2;
    const int wn   = w & 3;

    const __nv_bfloat16* Qb = g_q + (size_t)bz * SS * INNER;
    const __nv_bfloat16* Kb = g_k + (size_t)bz * SS * INNER;

    #pragma unroll
    for (int q = 0; q < 4; q++) {
        int v = tid + q * 256;
        int r = v >> 3, c8 = (v & 7) * 8;
        *reinterpret_cast<uint4*>(&Qs[r][c8]) =
            *reinterpret_cast<const uint4*>(&Qb[(size_t)(m0 + r) * INNER + c8]);
        *reinterpret_cast<uint4*>(&Ks[r][c8]) =
            *reinterpret_cast<const uint4*>(&Kb[(size_t)(n0 + r) * INNER + c8]);
    }
    __syncthreads();

    float acc[4][4][4];
    #pragma unroll
    for (int i = 0; i < 4; i++)
        #pragma unroll
        for (int j = 0; j < 4; j++)
            #pragma unroll
            for (int r = 0; r < 4; r++) acc[i][j][r] = 0.f;

    const uint32_t asQ = smem_u32(&Qs[0][0]);
    const uint32_t asK = smem_u32(&Ks[0][0]);
    const uint32_t aoff = (uint32_t)((wm * 64 + (lane & 15)) * Q_STRIDE + (lane >> 4) * 8) * 2;
    const uint32_t boff = (uint32_t)((wn * 32 + ((lane >> 4) & 1) * 8 + (lane & 7)) * Q_STRIDE
                                     + ((lane >> 3) & 1) * 8) * 2;

    #pragma unroll
    for (int ks = 0; ks < 4; ks++) {
        uint32_t a[4][4], bfr[2][4];
        #pragma unroll
        for (int i = 0; i < 4; i++)
            ldsm4(a[i], asQ + aoff + (uint32_t)(i * 16 * Q_STRIDE + ks * 16) * 2);
        #pragma unroll
        for (int jp = 0; jp < 2; jp++)
            ldsm4(bfr[jp], asK + boff + (uint32_t)(jp * 16 * Q_STRIDE + ks * 16) * 2);
        #pragma unroll
        for (int i = 0; i < 4; i++)
            #pragma unroll
            for (int j = 0; j < 4; j++)
                mma_bf16(acc[i][j], a[i], bfr[j >> 1][(j & 1) * 2], bfr[j >> 1][(j & 1) * 2 + 1]);
    }

    #pragma unroll
    for (int j = 0; j < 4; j++) {
        const int n = n0 + wn * 32 + j * 8 + (lane & 3) * 2;
        const float p0 = __ldg(&mask[b * SS + n]);
        const float p1 = __ldg(&mask[b * SS + n + 1]);
        #pragma unroll
        for (int i = 0; i < 4; i++) {
            #pragma unroll
            for (int h = 0; h < 2; h++) {
                const int m = m0 + wm * 64 + i * 16 + (lane >> 2) + h * 8;
                float lo = acc[i][j][2 * h]     * p0 - (1.0f - p0) * NEG_INF_F;
                float hi = acc[i][j][2 * h + 1] * p1 - (1.0f - p1) * NEG_INF_F;
                if (m > n)     lo -= NEG_INF_F;
                if (m > n + 1) hi -= NEG_INF_F;
                float2 v = make_float2(lo * 0.125f, hi * 0.125f);
                __stcs(reinterpret_cast<float2*>(&out[((size_t)bz * SS + m) * SS + n]), v);
            }
        }
    }
}

extern "C" void kernel_launch(void* const* d_in, const int* in_sizes, int n_in,
                              void* d_out, int out_size) {
    const float* X    = (const float*)d_in[0];  // [16,512,768]
    const float* msk  = (const float*)d_in[1];  // [16,512]
    const float* W    = (const float*)d_in[2];  // [768,1152]
    const float* bias = (const float*)d_in[3];  // [1152]
    float* out = (float*)d_out;                 // [16,9,512,512]

    rope_table_kernel<<<(SS * 32) / 256, 256>>>();

    const int cvt_chunks = (BB * SS * HH + HH * ND) / 4;
    convert_kernel<<<(cvt_chunks + 255) / 256, 256>>>(X, W);

    dim3 gridA(ND / 128, (BB * SS) / 128);      // (9, 64)
    proj_rope_kernel<<<gridA, 256>>>(bias);

    dim3 gridB(SS / 128, SS / 128, BB * ENT);   // (4, 4, 144)
    qk_kernel<<<gridB, 256>>>(msk, out);
}

// round 10
// speedup vs baseline: 5.1203x; 1.0231x over previous
#include <cuda_runtime.h>
#include <cuda_bf16.h>
#include <math.h>
#include <stdint.h>

#define ENT   9
#define INNER 64
#define BB    16
#define SS    512
#define HH    768
#define ND    (ENT * INNER * 2)   // 1152
#define NEG_INF_F 1000000000000.0f

__device__ __nv_bfloat16 g_xb[BB * SS * HH];
__device__ __nv_bfloat16 g_wb[HH * ND];
__device__ __nv_bfloat16 g_q[BB * ENT * SS * INNER];
__device__ __nv_bfloat16 g_k[BB * ENT * SS * INNER];
__device__ float g_rope[SS * 64];   // (cos,sin) per (s, d/2)

__device__ __forceinline__ uint32_t smem_u32(const void* p) {
    return (uint32_t)__cvta_generic_to_shared(p);
}
__device__ __forceinline__ uint32_t pk_bf2(float lo, float hi) {
    uint32_t r; asm("cvt.rn.bf16x2.f32 %0, %1, %2;" : "=r"(r) : "f"(hi), "f"(lo)); return r;
}
__device__ __forceinline__ void ldsm4(uint32_t* r, uint32_t addr) {
    asm volatile("ldmatrix.sync.aligned.m8n8.x4.shared.b16 {%0,%1,%2,%3}, [%4];"
        : "=r"(r[0]), "=r"(r[1]), "=r"(r[2]), "=r"(r[3]) : "r"(addr));
}
__device__ __forceinline__ void ldsm4t(uint32_t* r, uint32_t addr) {
    asm volatile("ldmatrix.sync.aligned.m8n8.x4.trans.shared.b16 {%0,%1,%2,%3}, [%4];"
        : "=r"(r[0]), "=r"(r[1]), "=r"(r[2]), "=r"(r[3]) : "r"(addr));
}
__device__ __forceinline__ void mma_bf16(float* c, const uint32_t* a, uint32_t b0, uint32_t b1) {
    asm volatile("mma.sync.aligned.m16n8k16.row.col.f32.bf16.bf16.f32 "
        "{%0,%1,%2,%3}, {%4,%5,%6,%7}, {%8,%9}, {%0,%1,%2,%3};"
        : "+f"(c[0]), "+f"(c[1]), "+f"(c[2]), "+f"(c[3])
        : "r"(a[0]), "r"(a[1]), "r"(a[2]), "r"(a[3]), "r"(b0), "r"(b1));
}
__device__ __forceinline__ void cp16(uint32_t dst, const void* src) {
    asm volatile("cp.async.cg.shared.global [%0], [%1], 16;" :: "r"(dst), "l"(src));
}
__device__ __forceinline__ void cp_commit() { asm volatile("cp.async.commit_group;"); }
template<int N> __device__ __forceinline__ void cp_wait() {
    asm volatile("cp.async.wait_group %0;" :: "n"(N));
}

// ---------------------------------------------------------------------------
// Prep: fp32->bf16 convert of X and W + rope table, one kernel.
// ---------------------------------------------------------------------------
__global__ __launch_bounds__(256) void convert_kernel(
    const float* __restrict__ X, const float* __restrict__ W)
{
    const int xq = (BB * SS * HH) / 4;   // 1572864
    const int wq = (HH * ND) / 4;        //  221184
    int i = blockIdx.x * blockDim.x + threadIdx.x;
    if (i < xq) {
        float4 v = *reinterpret_cast<const float4*>(X + 4 * (size_t)i);
        uint2 p = make_uint2(pk_bf2(v.x, v.y), pk_bf2(v.z, v.w));
        *reinterpret_cast<uint2*>(g_xb + 4 * (size_t)i) = p;
    } else if (i < xq + wq) {
        int j = i - xq;
        float4 v = *reinterpret_cast<const float4*>(W + 4 * (size_t)j);
        uint2 p = make_uint2(pk_bf2(v.x, v.y), pk_bf2(v.z, v.w));
        *reinterpret_cast<uint2*>(g_wb + 4 * (size_t)j) = p;
    } else {
        int j = i - xq - wq;             // 0..16383 = s*32 + p
        if (j < SS * 32) {
            int s = j >> 5, p = j & 31;
            float freq = exp2f(-0.41524101186092f * (float)p);
            float sn, cs;
            sincosf((float)s * freq, &sn, &cs);
            g_rope[2 * j]     = cs;
            g_rope[2 * j + 1] = sn;
        }
    }
}

// ---------------------------------------------------------------------------
// Kernel A: proj = Xb @ Wb + b (bf16 HMMA), RoPE via table, bf16 scatter.
// Block 128x128, ktile 64, 2-stage cp.async, 8 warps 2x4, warp 64x32.
// Dynamic smem ~70 KB.
// ---------------------------------------------------------------------------
#define A_ST 72    // bf16 per row (64 + 8 pad)
#define B_ST 136   // bf16 per row (128 + 8 pad)
#define A_BUF_B (128 * A_ST * 2)   // 18432
#define B_BUF_B (64 * B_ST * 2)    // 17408
__global__ __launch_bounds__(256) void proj_rope_kernel(
    const float* __restrict__ bias)   // [1152]
{
    extern __shared__ __align__(16) char smem[];
    // layout: A[2] then B[2]
    const uint32_t asA = smem_u32(smem);
    const uint32_t asB = asA + 2 * A_BUF_B;

    const int tid  = threadIdx.x;
    const int lane = tid & 31;
    const int w    = tid >> 5;
    const int wm   = w >> 2;          // 0..1
    const int wn   = w & 3;           // 0..3
    const int m0   = blockIdx.y * 128;
    const int n0   = blockIdx.x * 128;

    float acc[4][4][4];
    #pragma unroll
    for (int i = 0; i < 4; i++)
        #pragma unroll
        for (int j = 0; j < 4; j++)
            #pragma unroll
            for (int r = 0; r < 4; r++) acc[i][j][r] = 0.f;

    // staging slots: A 128x64 (8 chunks/row of 16B), B 64x128 (16 chunks/row)
    const int ar0 = tid >> 3, ac0 = (tid & 7) * 8;     // rows 0..31 (+32i)
    const int br0 = tid >> 4, bc0 = (tid & 15) * 8;    // rows 0..15 (+16i)

    auto stage = [&](int buf, int t) {
        const int k0 = t * 64;
        const uint32_t aB = asA + (uint32_t)buf * A_BUF_B;
        const uint32_t bB = asB + (uint32_t)buf * B_BUF_B;
        #pragma unroll
        for (int i = 0; i < 4; i++) {
            const int r = ar0 + i * 32;
            cp16(aB + (uint32_t)(r * A_ST + ac0) * 2,
                 g_xb + (size_t)(m0 + r) * HH + k0 + ac0);
        }
        #pragma unroll
        for (int i = 0; i < 4; i++) {
            const int r = br0 + i * 16;
            cp16(bB + (uint32_t)(r * B_ST + bc0) * 2,
                 g_wb + (size_t)(k0 + r) * ND + n0 + bc0);
        }
    };

    const uint32_t aoff = (uint32_t)((wm * 64 + (lane & 15)) * A_ST + (lane >> 4) * 8) * 2;
    const uint32_t boff = (uint32_t)((((lane >> 3) & 1) * 8 + (lane & 7)) * B_ST
                                     + wn * 32 + ((lane >> 4) & 1) * 8) * 2;

    stage(0, 0);
    cp_commit();

    const int NT = HH / 64;   // 12
    for (int t = 0; t < NT; t++) {
        const int buf = t & 1;
        if (t < NT - 1) { stage(buf ^ 1, t + 1); cp_commit(); cp_wait<1>(); }
        else           { cp_wait<0>(); }
        __syncthreads();

        const uint32_t abase = asA + (uint32_t)buf * A_BUF_B;
        const uint32_t bbase = asB + (uint32_t)buf * B_BUF_B;
        #pragma unroll
        for (int ks = 0; ks < 4; ks++) {
            uint32_t a[4][4], b[2][4];
            #pragma unroll
            for (int i = 0; i < 4; i++)
                ldsm4(a[i], abase + aoff + (uint32_t)(i * 16 * A_ST + ks * 16) * 2);
            #pragma unroll
            for (int jp = 0; jp < 2; jp++)
                ldsm4t(b[jp], bbase + boff + (uint32_t)(ks * 16 * B_ST) * 2 + jp * 32);
            #pragma unroll
            for (int i = 0; i < 4; i++)
                #pragma unroll
                for (int j = 0; j < 4; j++)
                    mma_bf16(acc[i][j], a[i], b[j >> 1][(j & 1) * 2], b[j >> 1][(j & 1) * 2 + 1]);
        }
        __syncthreads();
    }

    // Epilogue: bias + RoPE (table), bf16 scatter.
    #pragma unroll
    for (int j = 0; j < 4; j++) {
        const int n = n0 + wn * 32 + j * 8 + (lane & 3) * 2;
        const int head = n >> 7;
        const int wloc = n & 127;
        const bool is_q = (wloc < 64);
        const int d  = wloc & 63;
        const float b0f = __ldg(&bias[n]);
        const float b1f = __ldg(&bias[n + 1]);
        __nv_bfloat16* dst = is_q ? g_q : g_k;
        #pragma unroll
        for (int i = 0; i < 4; i++) {
            #pragma unroll
            for (int h = 0; h < 2; h++) {
                const int m = m0 + wm * 64 + i * 16 + (lane >> 2) + h * 8;
                const int bb = m >> 9;
                const int s  = m & 511;
                const float2 r2 = *reinterpret_cast<const float2*>(&g_rope[s * 64 + d]);
                const float v0 = acc[i][j][2 * h]     + b0f;
                const float v1 = acc[i][j][2 * h + 1] + b1f;
                const float o0 = v0 * r2.x - v1 * r2.y;
                const float o1 = v1 * r2.x + v0 * r2.y;
                const int base = (((bb * ENT + head) * SS) + s) * INNER + d;
                *reinterpret_cast<uint32_t*>(&dst[base]) = pk_bf2(o0, o1);
            }
        }
    }
}

// ---------------------------------------------------------------------------
// Kernel B: per (b,h): logits = Q K^T (bf16 HMMA), mask + causal + scale.
// Block 128x64, 8 warps 4x2, warp tile 32x32 (acc 32 floats),
// 3 CTAs/SM target, streaming fp32 stores.
// ---------------------------------------------------------------------------
#define Q_ST 72
__global__ __launch_bounds__(256, 3) void qk_kernel(
    const float* __restrict__ mask,   // [16, 512]
    float* __restrict__ out)          // [16, 9, 512, 512]
{
    __shared__ __align__(16) __nv_bfloat16 Qs[128][Q_ST];
    __shared__ __align__(16) __nv_bfloat16 Ks[64][Q_ST];

    const int bz = blockIdx.z;
    const int b  = bz / ENT;
    const int m0 = blockIdx.y * 128;
    const int n0 = blockIdx.x * 64;

    const int tid  = threadIdx.x;
    const int lane = tid & 31;
    const int w    = tid >> 5;
    const int wm   = w >> 1;    // 0..3
    const int wn   = w & 1;     // 0..1

    const __nv_bfloat16* Qb = g_q + (size_t)bz * SS * INNER;
    const __nv_bfloat16* Kb = g_k + (size_t)bz * SS * INNER;

    #pragma unroll
    for (int q = 0; q < 4; q++) {
        int v = tid + q * 256;            // 0..1023
        int r = v >> 3, c8 = (v & 7) * 8;
        *reinterpret_cast<uint4*>(&Qs[r][c8]) =
            *reinterpret_cast<const uint4*>(&Qb[(size_t)(m0 + r) * INNER + c8]);
    }
    #pragma unroll
    for (int q = 0; q < 2; q++) {
        int v = tid + q * 256;            // 0..511
        int r = v >> 3, c8 = (v & 7) * 8;
        *reinterpret_cast<uint4*>(&Ks[r][c8]) =
            *reinterpret_cast<const uint4*>(&Kb[(size_t)(n0 + r) * INNER + c8]);
    }
    __syncthreads();

    float acc[2][4][4];
    #pragma unroll
    for (int i = 0; i < 2; i++)
        #pragma unroll
        for (int j = 0; j < 4; j++)
            #pragma unroll
            for (int r = 0; r < 4; r++) acc[i][j][r] = 0.f;

    const uint32_t asQ = smem_u32(&Qs[0][0]);
    const uint32_t asK = smem_u32(&Ks[0][0]);
    const uint32_t aoff = (uint32_t)((wm * 32 + (lane & 15)) * Q_ST + (lane >> 4) * 8) * 2;
    const uint32_t boff = (uint32_t)((wn * 32 + ((lane >> 4) & 1) * 8 + (lane & 7)) * Q_ST
                                     + ((lane >> 3) & 1) * 8) * 2;

    #pragma unroll
    for (int ks = 0; ks < 4; ks++) {
        uint32_t a[2][4], bfr[2][4];
        #pragma unroll
        for (int i = 0; i < 2; i++)
            ldsm4(a[i], asQ + aoff + (uint32_t)(i * 16 * Q_ST + ks * 16) * 2);
        #pragma unroll
        for (int jp = 0; jp < 2; jp++)
            ldsm4(bfr[jp], asK + boff + (uint32_t)(jp * 16 * Q_ST + ks * 16) * 2);
        #pragma unroll
        for (int i = 0; i < 2; i++)
            #pragma unroll
            for (int j = 0; j < 4; j++)
                mma_bf16(acc[i][j], a[i], bfr[j >> 1][(j & 1) * 2], bfr[j >> 1][(j & 1) * 2 + 1]);
    }

    #pragma unroll
    for (int j = 0; j < 4; j++) {
        const int n = n0 + wn * 32 + j * 8 + (lane & 3) * 2;
        const float p0 = __ldg(&mask[b * SS + n]);
        const float p1 = __ldg(&mask[b * SS + n + 1]);
        #pragma unroll
        for (int i = 0; i < 2; i++) {
            #pragma unroll
            for (int h = 0; h < 2; h++) {
                const int m = m0 + wm * 32 + i * 16 + (lane >> 2) + h * 8;
                float lo = acc[i][j][2 * h]     * p0 - (1.0f - p0) * NEG_INF_F;
                float hi = acc[i][j][2 * h + 1] * p1 - (1.0f - p1) * NEG_INF_F;
                if (m > n)     lo -= NEG_INF_F;
                if (m > n + 1) hi -= NEG_INF_F;
                float2 v = make_float2(lo * 0.125f, hi * 0.125f);
                __stcs(reinterpret_cast<float2*>(&out[((size_t)bz * SS + m) * SS + n]), v);
            }
        }
    }
}

extern "C" void kernel_launch(void* const* d_in, const int* in_sizes, int n_in,
                              void* d_out, int out_size) {
    const float* X    = (const float*)d_in[0];  // [16,512,768]
    const float* msk  = (const float*)d_in[1];  // [16,512]
    const float* W    = (const float*)d_in[2];  // [768,1152]
    const float* bias = (const float*)d_in[3];  // [1152]
    float* out = (float*)d_out;                 // [16,9,512,512]

    const int cvt_items = (BB * SS * HH + HH * ND) / 4 + SS * 32;
    convert_kernel<<<(cvt_items + 255) / 256, 256>>>(X, W);

    const int proj_smem = 2 * A_BUF_B + 2 * B_BUF_B;  // 71680
    static bool attr_set = false;
    if (!attr_set) {
        cudaFuncSetAttribute(proj_rope_kernel,
                             cudaFuncAttributeMaxDynamicSharedMemorySize, proj_smem);
        attr_set = true;
    }
    dim3 gridA(ND / 128, (BB * SS) / 128);      // (9, 64)
    proj_rope_kernel<<<gridA, 256, proj_smem>>>(bias);

    dim3 gridB(SS / 64, SS / 128, BB * ENT);    // (8, 4, 144)
    qk_kernel<<<gridB, 256>>>(msk, out);
}

// round 11
// speedup vs baseline: 5.4605x; 1.0664x over previous
#include <cuda_runtime.h>
#include <cuda_bf16.h>
#include <math.h>
#include <stdint.h>

#define ENT   9
#define INNER 64
#define BB    16
#define SS    512
#define HH    768
#define ND    (ENT * INNER * 2)   // 1152
#define NEG_INF_F 1000000000000.0f

__device__ __nv_bfloat16 g_xb[BB * SS * HH];
__device__ __nv_bfloat16 g_wb[HH * ND];
__device__ __nv_bfloat16 g_q[BB * ENT * SS * INNER];
__device__ __nv_bfloat16 g_k[BB * ENT * SS * INNER];
__device__ float g_rope[SS * 64];   // (cos,sin) per (s, d/2)

__device__ __forceinline__ uint32_t smem_u32(const void* p) {
    return (uint32_t)__cvta_generic_to_shared(p);
}
__device__ __forceinline__ uint32_t pk_bf2(float lo, float hi) {
    uint32_t r; asm("cvt.rn.bf16x2.f32 %0, %1, %2;" : "=r"(r) : "f"(hi), "f"(lo)); return r;
}
__device__ __forceinline__ void ldsm4(uint32_t* r, uint32_t addr) {
    asm volatile("ldmatrix.sync.aligned.m8n8.x4.shared.b16 {%0,%1,%2,%3}, [%4];"
        : "=r"(r[0]), "=r"(r[1]), "=r"(r[2]), "=r"(r[3]) : "r"(addr));
}
__device__ __forceinline__ void ldsm4t(uint32_t* r, uint32_t addr) {
    asm volatile("ldmatrix.sync.aligned.m8n8.x4.trans.shared.b16 {%0,%1,%2,%3}, [%4];"
        : "=r"(r[0]), "=r"(r[1]), "=r"(r[2]), "=r"(r[3]) : "r"(addr));
}
__device__ __forceinline__ void mma_bf16(float* c, const uint32_t* a, uint32_t b0, uint32_t b1) {
    asm volatile("mma.sync.aligned.m16n8k16.row.col.f32.bf16.bf16.f32 "
        "{%0,%1,%2,%3}, {%4,%5,%6,%7}, {%8,%9}, {%0,%1,%2,%3};"
        : "+f"(c[0]), "+f"(c[1]), "+f"(c[2]), "+f"(c[3])
        : "r"(a[0]), "r"(a[1]), "r"(a[2]), "r"(a[3]), "r"(b0), "r"(b1));
}
__device__ __forceinline__ void cp16(uint32_t dst, const void* src) {
    asm volatile("cp.async.cg.shared.global [%0], [%1], 16;" :: "r"(dst), "l"(src));
}
__device__ __forceinline__ void cp_commit() { asm volatile("cp.async.commit_group;"); }
template<int N> __device__ __forceinline__ void cp_wait() {
    asm volatile("cp.async.wait_group %0;" :: "n"(N));
}

// ---------------------------------------------------------------------------
// Prep: fp32->bf16 convert of X and W + rope table. 2 chunks per thread.
// ---------------------------------------------------------------------------
__global__ __launch_bounds__(256) void convert_kernel(
    const float* __restrict__ X, const float* __restrict__ W)
{
    const int xq = (BB * SS * HH) / 4;   // 1572864
    const int wq = (HH * ND) / 4;        //  221184
    const int base = (blockIdx.x * blockDim.x + threadIdx.x) * 2;
    #pragma unroll
    for (int u = 0; u < 2; u++) {
        const int i = base + u;
        if (i < xq) {
            float4 v = *reinterpret_cast<const float4*>(X + 4 * (size_t)i);
            uint2 p = make_uint2(pk_bf2(v.x, v.y), pk_bf2(v.z, v.w));
            *reinterpret_cast<uint2*>(g_xb + 4 * (size_t)i) = p;
        } else if (i < xq + wq) {
            int j = i - xq;
            float4 v = *reinterpret_cast<const float4*>(W + 4 * (size_t)j);
            uint2 p = make_uint2(pk_bf2(v.x, v.y), pk_bf2(v.z, v.w));
            *reinterpret_cast<uint2*>(g_wb + 4 * (size_t)j) = p;
        } else {
            int j = i - xq - wq;
            if (j < SS * 32) {
                int s = j >> 5, p = j & 31;
                float freq = exp2f(-0.41524101186092f * (float)p);
                float sn, cs;
                sincosf((float)s * freq, &sn, &cs);
                g_rope[2 * j]     = cs;
                g_rope[2 * j + 1] = sn;
            }
        }
    }
}

// ---------------------------------------------------------------------------
// Kernel A: proj = Xb @ Wb + b (bf16 HMMA), RoPE via table, bf16 scatter.
// Block 128x128, ktile 64, 2-stage cp.async, 8 warps 2x4, warp 64x32.
// ---------------------------------------------------------------------------
#define A_ST 72    // bf16 per row (64 + 8 pad)
#define B_ST 136   // bf16 per row (128 + 8 pad)
#define A_BUF_B (128 * A_ST * 2)   // 18432
#define B_BUF_B (64 * B_ST * 2)    // 17408
__global__ __launch_bounds__(256) void proj_rope_kernel(
    const float* __restrict__ bias)   // [1152]
{
    extern __shared__ __align__(16) char smem[];
    const uint32_t asA = smem_u32(smem);
    const uint32_t asB = asA + 2 * A_BUF_B;

    const int tid  = threadIdx.x;
    const int lane = tid & 31;
    const int w    = tid >> 5;
    const int wm   = w >> 2;
    const int wn   = w & 3;
    const int m0   = blockIdx.y * 128;
    const int n0   = blockIdx.x * 128;

    float acc[4][4][4];
    #pragma unroll
    for (int i = 0; i < 4; i++)
        #pragma unroll
        for (int j = 0; j < 4; j++)
            #pragma unroll
            for (int r = 0; r < 4; r++) acc[i][j][r] = 0.f;

    const int ar0 = tid >> 3, ac0 = (tid & 7) * 8;
    const int br0 = tid >> 4, bc0 = (tid & 15) * 8;

    auto stage = [&](int buf, int t) {
        const int k0 = t * 64;
        const uint32_t aB = asA + (uint32_t)buf * A_BUF_B;
        const uint32_t bB = asB + (uint32_t)buf * B_BUF_B;
        #pragma unroll
        for (int i = 0; i < 4; i++) {
            const int r = ar0 + i * 32;
            cp16(aB + (uint32_t)(r * A_ST + ac0) * 2,
                 g_xb + (size_t)(m0 + r) * HH + k0 + ac0);
        }
        #pragma unroll
        for (int i = 0; i < 4; i++) {
            const int r = br0 + i * 16;
            cp16(bB + (uint32_t)(r * B_ST + bc0) * 2,
                 g_wb + (size_t)(k0 + r) * ND + n0 + bc0);
        }
    };

    const uint32_t aoff = (uint32_t)((wm * 64 + (lane & 15)) * A_ST + (lane >> 4) * 8) * 2;
    const uint32_t boff = (uint32_t)((((lane >> 3) & 1) * 8 + (lane & 7)) * B_ST
                                     + wn * 32 + ((lane >> 4) & 1) * 8) * 2;

    stage(0, 0);
    cp_commit();

    const int NT = HH / 64;   // 12
    for (int t = 0; t < NT; t++) {
        const int buf = t & 1;
        if (t < NT - 1) { stage(buf ^ 1, t + 1); cp_commit(); cp_wait<1>(); }
        else           { cp_wait<0>(); }
        __syncthreads();

        const uint32_t abase = asA + (uint32_t)buf * A_BUF_B;
        const uint32_t bbase = asB + (uint32_t)buf * B_BUF_B;
        #pragma unroll
        for (int ks = 0; ks < 4; ks++) {
            uint32_t a[4][4], b[2][4];
            #pragma unroll
            for (int i = 0; i < 4; i++)
                ldsm4(a[i], abase + aoff + (uint32_t)(i * 16 * A_ST + ks * 16) * 2);
            #pragma unroll
            for (int jp = 0; jp < 2; jp++)
                ldsm4t(b[jp], bbase + boff + (uint32_t)(ks * 16 * B_ST) * 2 + jp * 32);
            #pragma unroll
            for (int i = 0; i < 4; i++)
                #pragma unroll
                for (int j = 0; j < 4; j++)
                    mma_bf16(acc[i][j], a[i], b[j >> 1][(j & 1) * 2], b[j >> 1][(j & 1) * 2 + 1]);
        }
        __syncthreads();
    }

    #pragma unroll
    for (int j = 0; j < 4; j++) {
        const int n = n0 + wn * 32 + j * 8 + (lane & 3) * 2;
        const int head = n >> 7;
        const int wloc = n & 127;
        const bool is_q = (wloc < 64);
        const int d  = wloc & 63;
        const float b0f = __ldg(&bias[n]);
        const float b1f = __ldg(&bias[n + 1]);
        __nv_bfloat16* dst = is_q ? g_q : g_k;
        #pragma unroll
        for (int i = 0; i < 4; i++) {
            #pragma unroll
            for (int h = 0; h < 2; h++) {
                const int m = m0 + wm * 64 + i * 16 + (lane >> 2) + h * 8;
                const int bb = m >> 9;
                const int s  = m & 511;
                const float2 r2 = *reinterpret_cast<const float2*>(&g_rope[s * 64 + d]);
                const float v0 = acc[i][j][2 * h]     + b0f;
                const float v1 = acc[i][j][2 * h + 1] + b1f;
                const float o0 = v0 * r2.x - v1 * r2.y;
                const float o1 = v1 * r2.x + v0 * r2.y;
                const int base = (((bb * ENT + head) * SS) + s) * INNER + d;
                *reinterpret_cast<uint32_t*>(&dst[base]) = pk_bf2(o0, o1);
            }
        }
    }
}

// ---------------------------------------------------------------------------
// Kernel B: per (b,h): logits = Q K^T (bf16 HMMA), mask + causal + scale.
// Block 128x64. Fully strict-lower blocks (m0 >= n0+64) take a store-only
// path: every element is causally masked, so out = (-(1-pad)*NEG - NEG)/8
// (the O(10) logit term is ~8e-11 of the output norm — far below tolerance).
// ---------------------------------------------------------------------------
#define Q_ST 72
__global__ __launch_bounds__(256, 3) void qk_kernel(
    const float* __restrict__ mask,   // [16, 512]
    float* __restrict__ out)          // [16, 9, 512, 512]
{
    __shared__ __align__(16) __nv_bfloat16 Qs[128][Q_ST];
    __shared__ __align__(16) __nv_bfloat16 Ks[64][Q_ST];

    const int bz = blockIdx.z;
    const int b  = bz / ENT;
    const int m0 = blockIdx.y * 128;
    const int n0 = blockIdx.x * 64;

    const int tid  = threadIdx.x;
    const int lane = tid & 31;
    const int w    = tid >> 5;
    const int wm   = w >> 1;
    const int wn   = w & 1;

    if (m0 >= n0 + 64) {
        // store-only: value depends only on n
        const int c4 = (tid & 15) * 4;          // col group 0..60
        const int r0 = tid >> 4;                // 0..15
        const float4 p = *reinterpret_cast<const float4*>(&mask[b * SS + n0 + c4]);
        float4 v;
        v.x = (-(1.0f - p.x) * NEG_INF_F - NEG_INF_F) * 0.125f;
        v.y = (-(1.0f - p.y) * NEG_INF_F - NEG_INF_F) * 0.125f;
        v.z = (-(1.0f - p.z) * NEG_INF_F - NEG_INF_F) * 0.125f;
        v.w = (-(1.0f - p.w) * NEG_INF_F - NEG_INF_F) * 0.125f;
        float* base = &out[((size_t)bz * SS + m0 + r0) * SS + n0 + c4];
        #pragma unroll
        for (int i = 0; i < 8; i++)
            __stcs(reinterpret_cast<float4*>(base + (size_t)i * 16 * SS), v);
        return;
    }

    const __nv_bfloat16* Qb = g_q + (size_t)bz * SS * INNER;
    const __nv_bfloat16* Kb = g_k + (size_t)bz * SS * INNER;

    #pragma unroll
    for (int q = 0; q < 4; q++) {
        int v = tid + q * 256;
        int r = v >> 3, c8 = (v & 7) * 8;
        *reinterpret_cast<uint4*>(&Qs[r][c8]) =
            *reinterpret_cast<const uint4*>(&Qb[(size_t)(m0 + r) * INNER + c8]);
    }
    #pragma unroll
    for (int q = 0; q < 2; q++) {
        int v = tid + q * 256;
        int r = v >> 3, c8 = (v & 7) * 8;
        *reinterpret_cast<uint4*>(&Ks[r][c8]) =
            *reinterpret_cast<const uint4*>(&Kb[(size_t)(n0 + r) * INNER + c8]);
    }
    __syncthreads();

    float acc[2][4][4];
    #pragma unroll
    for (int i = 0; i < 2; i++)
        #pragma unroll
        for (int j = 0; j < 4; j++)
            #pragma unroll
            for (int r = 0; r < 4; r++) acc[i][j][r] = 0.f;

    const uint32_t asQ = smem_u32(&Qs[0][0]);
    const uint32_t asK = smem_u32(&Ks[0][0]);
    const uint32_t aoff = (uint32_t)((wm * 32 + (lane & 15)) * Q_ST + (lane >> 4) * 8) * 2;
    const uint32_t boff = (uint32_t)((wn * 32 + ((lane >> 4) & 1) * 8 + (lane & 7)) * Q_ST
                                     + ((lane >> 3) & 1) * 8) * 2;

    #pragma unroll
    for (int ks = 0; ks < 4; ks++) {
        uint32_t a[2][4], bfr[2][4];
        #pragma unroll
        for (int i = 0; i < 2; i++)
            ldsm4(a[i], asQ + aoff + (uint32_t)(i * 16 * Q_ST + ks * 16) * 2);
        #pragma unroll
        for (int jp = 0; jp < 2; jp++)
            ldsm4(bfr[jp], asK + boff + (uint32_t)(jp * 16 * Q_ST + ks * 16) * 2);
        #pragma unroll
        for (int i = 0; i < 2; i++)
            #pragma unroll
            for (int j = 0; j < 4; j++)
                mma_bf16(acc[i][j], a[i], bfr[j >> 1][(j & 1) * 2], bfr[j >> 1][(j & 1) * 2 + 1]);
    }

    #pragma unroll
    for (int j = 0; j < 4; j++) {
        const int n = n0 + wn * 32 + j * 8 + (lane & 3) * 2;
        const float p0 = __ldg(&mask[b * SS + n]);
        const float p1 = __ldg(&mask[b * SS + n + 1]);
        #pragma unroll
        for (int i = 0; i < 2; i++) {
            #pragma unroll
            for (int h = 0; h < 2; h++) {
                const int m = m0 + wm * 32 + i * 16 + (lane >> 2) + h * 8;
                float lo = acc[i][j][2 * h]     * p0 - (1.0f - p0) * NEG_INF_F;
                float hi = acc[i][j][2 * h + 1] * p1 - (1.0f - p1) * NEG_INF_F;
                if (m > n)     lo -= NEG_INF_F;
                if (m > n + 1) hi -= NEG_INF_F;
                float2 v = make_float2(lo * 0.125f, hi * 0.125f);
                __stcs(reinterpret_cast<float2*>(&out[((size_t)bz * SS + m) * SS + n]), v);
            }
        }
    }
}

extern "C" void kernel_launch(void* const* d_in, const int* in_sizes, int n_in,
                              void* d_out, int out_size) {
    const float* X    = (const float*)d_in[0];  // [16,512,768]
    const float* msk  = (const float*)d_in[1];  // [16,512]
    const float* W    = (const float*)d_in[2];  // [768,1152]
    const float* bias = (const float*)d_in[3];  // [1152]
    float* out = (float*)d_out;                 // [16,9,512,512]

    const int cvt_items = (BB * SS * HH + HH * ND) / 4 + SS * 32;
    const int cvt_threads = (cvt_items + 1) / 2;
    convert_kernel<<<(cvt_threads + 255) / 256, 256>>>(X, W);

    const int proj_smem = 2 * A_BUF_B + 2 * B_BUF_B;  // 71680
    static bool attr_set = false;
    if (!attr_set) {
        cudaFuncSetAttribute(proj_rope_kernel,
                             cudaFuncAttributeMaxDynamicSharedMemorySize, proj_smem);
        attr_set = true;
    }
    dim3 gridA(ND / 128, (BB * SS) / 128);      // (9, 64)
    proj_rope_kernel<<<gridA, 256, proj_smem>>>(bias);

    dim3 gridB(SS / 64, SS / 128, BB * ENT);    // (8, 4, 144)
    qk_kernel<<<gridB, 256>>>(msk, out);
}